// round 14
// baseline (speedup 1.0000x reference)
#include <cuda_runtime.h>
#include <math.h>
#include <stdint.h>

// Problem constants
#define BB   16
#define NN   2048
#define CIN  64
#define CC   256
#define MTOT (BB*NN)   // 32768
#define NBLK 16        // NN/128
#define NPAIRS 136     // NBLK*(NBLK+1)/2

// cp.async GEMM smem: 4 stages x (2560 A + 2560 B)
#define SMEMCA (8 * 2560 * 4)
// wide x_r GEMM smem: 4 stages x (2176 A + 4224 B) + 128 rsc
#define SMEMXR2 ((4 * (2176 + 4224) + 128) * 4)

// ---------------- scratch (device globals; no allocation allowed) ----------------
__device__ float g_h[MTOT*CC];
__device__ float g_q[MTOT*CC];
__device__ float g_v[MTOT*CC];
__device__ float g_u[MTOT*CC];
__device__ float g_attn[(size_t)BB*NN*NN];   // 256 MiB
__device__ float g_wr[4*CC*CC];              // rounded w2,wqk,wv,wt
__device__ float g_bnscale[3*CC];
__device__ float g_bnshift[3*CC];

// ---------------- BN precompute ----------------
__global__ void bn_prep(const float* __restrict__ g1, const float* __restrict__ b1,
                        const float* __restrict__ m1, const float* __restrict__ v1,
                        const float* __restrict__ g2, const float* __restrict__ b2,
                        const float* __restrict__ m2, const float* __restrict__ v2,
                        const float* __restrict__ g3, const float* __restrict__ b3,
                        const float* __restrict__ m3, const float* __restrict__ v3,
                        const float* __restrict__ bt)
{
    int c = threadIdx.x;
    float s;
    s = g1[c] * rsqrtf(v1[c] + 1e-5f);
    g_bnscale[c]       = s; g_bnshift[c]       = b1[c] - m1[c]*s;
    s = g2[c] * rsqrtf(v2[c] + 1e-5f);
    g_bnscale[256 + c] = s; g_bnshift[256 + c] = b2[c] - m2[c]*s;
    s = g3[c] * rsqrtf(v3[c] + 1e-5f);
    g_bnscale[512 + c] = s; g_bnshift[512 + c] = (bt[c] - m3[c])*s + b3[c];
}

__device__ __forceinline__ uint32_t cvt_tf32(float x) {
    uint32_t u;
    asm("cvt.rna.tf32.f32 %0, %1;" : "=r"(u) : "f"(x));
    return u;
}
__device__ __forceinline__ float cvt1(float x) { return __uint_as_float(cvt_tf32(x)); }

__device__ __forceinline__ float4 cvt4(float4 v) {
    float4 o;
    o.x = cvt1(v.x); o.y = cvt1(v.y); o.z = cvt1(v.z); o.w = cvt1(v.w);
    return o;
}

__device__ __forceinline__ uint32_t smem_u32(const void* p) {
    return (uint32_t)__cvta_generic_to_shared(p);
}
__device__ __forceinline__ void cp_async16(uint32_t dst, const void* src) {
    asm volatile("cp.async.cg.shared.global [%0], [%1], 16;\n" :: "r"(dst), "l"(src));
}

// ---------------- elementwise tf32 pre-round: 4 weights in one launch -----------
__global__ void round_w(float* __restrict__ dst,
                        const float* __restrict__ s0, const float* __restrict__ s1,
                        const float* __restrict__ s2, const float* __restrict__ s3)
{
    const float* srcs[4] = {s0, s1, s2, s3};
    int tid = blockIdx.x * 256 + threadIdx.x;
    int stride = gridDim.x * 256;
#pragma unroll
    for (int a = 0; a < 4; a++) {
        const float* s = srcs[a];
        float* d = dst + a * CC * CC;
        for (int i = tid * 4; i < CC * CC; i += stride * 4)
            *(float4*)&d[i] = cvt4(*(const float4*)&s[i]);
    }
}

// ====== first GEMM: h1 = cvt(relu(bn1(x @ w1^T))), K=64, raw inputs, cvt@STS =====
__global__ __launch_bounds__(256, 2)
void gemm_first(const float* __restrict__ A, const float* __restrict__ B,
                float* __restrict__ C,
                const float* __restrict__ p0, const float* __restrict__ p1)
{
    __shared__ __align__(16) float As[2][2560];
    __shared__ __align__(16) float Bs[2][2560];

    const int t    = threadIdx.x;
    const int lane = t & 31;
    const int wid  = t >> 5;
    const int wm   = wid >> 2;
    const int wn   = wid & 3;
    const int grp  = lane >> 2;
    const int qid  = lane & 3;
    const int m0   = blockIdx.y * 128;
    const int n0   = blockIdx.x * 128;

    const int idx0 = t, idx1 = t + 256;
    const float* aP0 = A + (long long)(m0 + (idx0 >> 2)) * CIN + (idx0 & 3) * 4;
    const float* aP1 = A + (long long)(m0 + (idx1 >> 2)) * CIN + (idx1 & 3) * 4;
    const float* bP0 = B + (long long)(n0 + (idx0 >> 2)) * CIN + (idx0 & 3) * 4;
    const float* bP1 = B + (long long)(n0 + (idx1 >> 2)) * CIN + (idx1 & 3) * 4;
    const int s0o = (idx0 >> 2) * 20 + (idx0 & 3) * 4;
    const int s1o = (idx1 >> 2) * 20 + (idx1 & 3) * 4;

    float acc[4][4][4];
#pragma unroll
    for (int i = 0; i < 4; i++)
#pragma unroll
        for (int j = 0; j < 4; j++)
#pragma unroll
            for (int e = 0; e < 4; e++) acc[i][j][e] = 0.f;

    float4 stA0, stA1, stB0, stB1;

#define FLDG(kit)                                                        \
    {                                                                    \
        stA0 = *(const float4*)(aP0 + (kit) * 16);                       \
        stA1 = *(const float4*)(aP1 + (kit) * 16);                       \
        stB0 = *(const float4*)(bP0 + (kit) * 16);                       \
        stB1 = *(const float4*)(bP1 + (kit) * 16);                       \
    }
#define FSTS(buf)                                                        \
    {                                                                    \
        *(float4*)&As[buf][s0o] = cvt4(stA0);                            \
        *(float4*)&As[buf][s1o] = cvt4(stA1);                            \
        *(float4*)&Bs[buf][s0o] = cvt4(stB0);                            \
        *(float4*)&Bs[buf][s1o] = cvt4(stB1);                            \
    }

    FLDG(0)
    FSTS(0)
    __syncthreads();

    for (int kit = 0, buf = 0; kit < 4; kit++, buf ^= 1) {
        const bool have_next = (kit + 1) < 4;
        if (have_next) FLDG(kit + 1)

        const float* Ab = As[buf];
        const float* Bb = Bs[buf];
#pragma unroll
        for (int ks = 0; ks < 16; ks += 8) {
            uint32_t a[4][4], b[4][2];
#pragma unroll
            for (int i = 0; i < 4; i++) {
                int rb = wm * 64 + i * 16 + grp;
                a[i][0] = __float_as_uint(Ab[(rb    ) * 20 + ks + qid]);
                a[i][1] = __float_as_uint(Ab[(rb + 8) * 20 + ks + qid]);
                a[i][2] = __float_as_uint(Ab[(rb    ) * 20 + ks + 4 + qid]);
                a[i][3] = __float_as_uint(Ab[(rb + 8) * 20 + ks + 4 + qid]);
            }
#pragma unroll
            for (int j = 0; j < 4; j++) {
                int nb = wn * 32 + j * 8 + grp;
                b[j][0] = __float_as_uint(Bb[nb * 20 + ks + qid]);
                b[j][1] = __float_as_uint(Bb[nb * 20 + ks + 4 + qid]);
            }
#pragma unroll
            for (int i = 0; i < 4; i++)
#pragma unroll
                for (int j = 0; j < 4; j++) {
                    asm volatile(
                        "mma.sync.aligned.m16n8k8.row.col.f32.tf32.tf32.f32 "
                        "{%0,%1,%2,%3}, {%4,%5,%6,%7}, {%8,%9}, {%0,%1,%2,%3};\n"
                        : "+f"(acc[i][j][0]), "+f"(acc[i][j][1]),
                          "+f"(acc[i][j][2]), "+f"(acc[i][j][3])
                        : "r"(a[i][0]), "r"(a[i][1]), "r"(a[i][2]), "r"(a[i][3]),
                          "r"(b[j][0]), "r"(b[j][1]));
                }
        }
        if (have_next) FSTS(buf ^ 1)
        __syncthreads();
    }
#undef FLDG
#undef FSTS

#pragma unroll
    for (int i = 0; i < 4; i++) {
        int r0 = m0 + wm * 64 + i * 16 + grp;
        int r1 = r0 + 8;
#pragma unroll
        for (int j = 0; j < 4; j++) {
            int c = n0 + wn * 32 + j * 8 + qid * 2;
            float s0 = p0[c], s1 = p0[c+1], h0 = p1[c], h1 = p1[c+1];
            float2 o0, o1;
            o0.x = cvt1(fmaxf(acc[i][j][0] * s0 + h0, 0.f));
            o0.y = cvt1(fmaxf(acc[i][j][1] * s1 + h1, 0.f));
            o1.x = cvt1(fmaxf(acc[i][j][2] * s0 + h0, 0.f));
            o1.y = cvt1(fmaxf(acc[i][j][3] * s1 + h1, 0.f));
            *(float2*)&C[(long long)r0 * CC + c] = o0;
            *(float2*)&C[(long long)r1 * CC + c] = o1;
        }
    }
}

// ================= cp.async 4-stage GEMM (operands pre-rounded tf32) =============
// EPI: 1 cvt(relu(acc*p0+p1)); 2 cvt(acc+p0); 3 cvt(acc);
//      5 raw symmetric; 6 fused final transposed
template<int EPI>
__global__ __launch_bounds__(256, 2)
void gemm_ca(const float* __restrict__ A, const float* __restrict__ B,
             float* __restrict__ C, int K,
             int lda, int ldb, int ldc,
             long long sA, long long sB, long long sC,
             const float* __restrict__ p0, const float* __restrict__ p1,
             const float* __restrict__ p2)
{
    extern __shared__ float smem[];

    const int z = blockIdx.z;
    A += (long long)z * sA;
    B += (long long)z * sB;

    const int t    = threadIdx.x;
    const int lane = t & 31;
    const int wid  = t >> 5;
    const int wm   = wid >> 2;
    const int wn   = wid & 3;
    const int grp  = lane >> 2;
    const int qid  = lane & 3;

    int m0, n0;
    if (EPI == 5) {
        int rem = blockIdx.x, bi = 0;
        while (rem >= NBLK - bi) { rem -= NBLK - bi; bi++; }
        m0 = bi * 128;
        n0 = (bi + rem) * 128;
    } else {
        m0 = blockIdx.y * 128;
        n0 = blockIdx.x * 128;
    }

    const int row = t >> 2, kq = t & 3;
    const float* aSrc0 = A + (long long)(m0 + row) * lda + kq * 4;
    const float* aSrc1 = aSrc0 + (long long)64 * lda;
    const float* bSrc0 = B + (long long)(n0 + row) * ldb + kq * 4;
    const float* bSrc1 = bSrc0 + (long long)64 * ldb;
    const int off0 = row * 20 + kq * 4;
    const int off1 = off0 + 64 * 20;

#define ISSUE(kit)                                                            \
    {                                                                         \
        int s_ = (kit) & 3;                                                   \
        float* As_ = smem + s_ * 2560;                                        \
        float* Bs_ = smem + 10240 + s_ * 2560;                                \
        long long ko_ = (long long)(kit) * 16;                                \
        cp_async16(smem_u32(As_ + off0), aSrc0 + ko_);                        \
        cp_async16(smem_u32(As_ + off1), aSrc1 + ko_);                        \
        cp_async16(smem_u32(Bs_ + off0), bSrc0 + ko_);                        \
        cp_async16(smem_u32(Bs_ + off1), bSrc1 + ko_);                        \
        asm volatile("cp.async.commit_group;\n");                             \
    }

    float acc[4][4][4];
#pragma unroll
    for (int i = 0; i < 4; i++)
#pragma unroll
        for (int j = 0; j < 4; j++)
#pragma unroll
            for (int e = 0; e < 4; e++) acc[i][j][e] = 0.f;

    const int kIters = K / 16;
    if (0 < kIters) ISSUE(0)
    if (1 < kIters) ISSUE(1)
    if (2 < kIters) ISSUE(2)

    for (int kit = 0; kit < kIters; kit++) {
        int rem = kIters - 1 - kit;
        if (rem >= 2)      asm volatile("cp.async.wait_group 2;\n");
        else if (rem == 1) asm volatile("cp.async.wait_group 1;\n");
        else               asm volatile("cp.async.wait_group 0;\n");
        __syncthreads();
        if (kit + 3 < kIters) ISSUE(kit + 3)

        const float* Ab = smem + (kit & 3) * 2560;
        const float* Bb = smem + 10240 + (kit & 3) * 2560;
#pragma unroll
        for (int ks = 0; ks < 16; ks += 8) {
            uint32_t a[4][4], b[4][2];
#pragma unroll
            for (int i = 0; i < 4; i++) {
                int rb = wm * 64 + i * 16 + grp;
                a[i][0] = __float_as_uint(Ab[(rb    ) * 20 + ks + qid]);
                a[i][1] = __float_as_uint(Ab[(rb + 8) * 20 + ks + qid]);
                a[i][2] = __float_as_uint(Ab[(rb    ) * 20 + ks + 4 + qid]);
                a[i][3] = __float_as_uint(Ab[(rb + 8) * 20 + ks + 4 + qid]);
            }
#pragma unroll
            for (int j = 0; j < 4; j++) {
                int nb = wn * 32 + j * 8 + grp;
                b[j][0] = __float_as_uint(Bb[nb * 20 + ks + qid]);
                b[j][1] = __float_as_uint(Bb[nb * 20 + ks + 4 + qid]);
            }
#pragma unroll
            for (int i = 0; i < 4; i++)
#pragma unroll
                for (int j = 0; j < 4; j++) {
                    asm volatile(
                        "mma.sync.aligned.m16n8k8.row.col.f32.tf32.tf32.f32 "
                        "{%0,%1,%2,%3}, {%4,%5,%6,%7}, {%8,%9}, {%0,%1,%2,%3};\n"
                        : "+f"(acc[i][j][0]), "+f"(acc[i][j][1]),
                          "+f"(acc[i][j][2]), "+f"(acc[i][j][3])
                        : "r"(a[i][0]), "r"(a[i][1]), "r"(a[i][2]), "r"(a[i][3]),
                          "r"(b[j][0]), "r"(b[j][1]));
                }
        }
    }
#undef ISSUE
    __syncthreads();

    float* Cz = C + (long long)z * sC;

    if (EPI != 6) {
#pragma unroll
        for (int i = 0; i < 4; i++) {
            int r0 = m0 + wm * 64 + i * 16 + grp;
            int r1 = r0 + 8;
#pragma unroll
            for (int j = 0; j < 4; j++) {
                int c = n0 + wn * 32 + j * 8 + qid * 2;
                float d0 = acc[i][j][0], d1 = acc[i][j][1];
                float d2 = acc[i][j][2], d3 = acc[i][j][3];
                float2 o0, o1;
                if (EPI == 5) {
                    o0 = make_float2(d0, d1);
                    o1 = make_float2(d2, d3);
                } else if (EPI == 3) {
                    o0 = make_float2(cvt1(d0), cvt1(d1));
                    o1 = make_float2(cvt1(d2), cvt1(d3));
                } else if (EPI == 1) {
                    float s0 = p0[c], s1 = p0[c+1], h0 = p1[c], h1 = p1[c+1];
                    o0.x = cvt1(fmaxf(d0 * s0 + h0, 0.f));
                    o0.y = cvt1(fmaxf(d1 * s1 + h1, 0.f));
                    o1.x = cvt1(fmaxf(d2 * s0 + h0, 0.f));
                    o1.y = cvt1(fmaxf(d3 * s1 + h1, 0.f));
                } else { // EPI == 2
                    float h0 = p0[c], h1 = p0[c+1];
                    o0 = make_float2(cvt1(d0 + h0), cvt1(d1 + h1));
                    o1 = make_float2(cvt1(d2 + h0), cvt1(d3 + h1));
                }
                *(float2*)&Cz[(long long)r0 * ldc + c] = o0;
                *(float2*)&Cz[(long long)r1 * ldc + c] = o1;
            }
        }
    }

    if (EPI == 5 && m0 != n0) {
        float* sm_t = smem;
#pragma unroll
        for (int half = 0; half < 2; half++) {
            __syncthreads();
            if (wm == half) {
#pragma unroll
                for (int i = 0; i < 4; i++) {
                    int rl = i * 16 + grp;
#pragma unroll
                    for (int j = 0; j < 4; j++) {
                        int c = wn * 32 + j * 8 + qid * 2;
                        sm_t[rl * 132 + c]           = acc[i][j][0];
                        sm_t[rl * 132 + c + 1]       = acc[i][j][1];
                        sm_t[(rl + 8) * 132 + c]     = acc[i][j][2];
                        sm_t[(rl + 8) * 132 + c + 1] = acc[i][j][3];
                    }
                }
            }
            __syncthreads();
            int c   = t >> 1;
            int seg = (t & 1) * 32;
            float* dst = Cz + (long long)(n0 + c) * ldc + m0 + half * 64 + seg;
#pragma unroll
            for (int s = 0; s < 32; s += 4) {
                float4 o;
                o.x = sm_t[(seg + s + 0) * 132 + c];
                o.y = sm_t[(seg + s + 1) * 132 + c];
                o.z = sm_t[(seg + s + 2) * 132 + c];
                o.w = sm_t[(seg + s + 3) * 132 + c];
                *(float4*)(dst + s) = o;
            }
        }
    }

    if (EPI == 6) {
#pragma unroll
        for (int i = 0; i < 4; i++) {
            int r0 = m0 + wm * 64 + i * 16 + grp;
            int r1 = r0 + 8;
#pragma unroll
            for (int j = 0; j < 4; j++) {
                int c = n0 + wn * 32 + j * 8 + qid * 2;
                float s0 = p0[c], s1 = p0[c+1], h0 = p1[c], h1 = p1[c+1];
                acc[i][j][0] = p2[(long long)r0 * ldc + c    ] + fmaxf(acc[i][j][0] * s0 + h0, 0.f);
                acc[i][j][1] = p2[(long long)r0 * ldc + c + 1] + fmaxf(acc[i][j][1] * s1 + h1, 0.f);
                acc[i][j][2] = p2[(long long)r1 * ldc + c    ] + fmaxf(acc[i][j][2] * s0 + h0, 0.f);
                acc[i][j][3] = p2[(long long)r1 * ldc + c + 1] + fmaxf(acc[i][j][3] * s1 + h1, 0.f);
            }
        }
        const int zb = m0 >> 11;
        const int ib = m0 & (NN - 1);
        float* outz = C + ((long long)zb * CC + n0) * NN;
        float* sm_t = smem;
#pragma unroll
        for (int half = 0; half < 2; half++) {
            __syncthreads();
            if (wm == half) {
#pragma unroll
                for (int i = 0; i < 4; i++) {
                    int rl = i * 16 + grp;
#pragma unroll
                    for (int j = 0; j < 4; j++) {
                        int c = wn * 32 + j * 8 + qid * 2;
                        sm_t[rl * 132 + c]           = acc[i][j][0];
                        sm_t[rl * 132 + c + 1]       = acc[i][j][1];
                        sm_t[(rl + 8) * 132 + c]     = acc[i][j][2];
                        sm_t[(rl + 8) * 132 + c + 1] = acc[i][j][3];
                    }
                }
            }
            __syncthreads();
            int c   = t >> 1;
            int seg = (t & 1) * 32;
            float* dst = outz + (long long)c * NN + ib + half * 64 + seg;
#pragma unroll
            for (int s = 0; s < 32; s += 4) {
                float4 o;
                o.x = sm_t[(seg + s + 0) * 132 + c];
                o.y = sm_t[(seg + s + 1) * 132 + c];
                o.z = sm_t[(seg + s + 2) * 132 + c];
                o.w = sm_t[(seg + s + 3) * 132 + c];
                *(float4*)(dst + s) = o;
            }
        }
    }
}

// ======= WIDE x_r GEMM: BM=128, BN=256 (attn read ONCE), 512 thr = 16 warps ======
// A trans [k][m] (attn), B trans [k][n] (v), both pre-rounded in gmem.
// u[r,c] = cvt( h[r,c] - acc * rscale[r] ), rscale from in-CTA colsum.
__global__ __launch_bounds__(512, 1)
void gemm_xr2(const float* __restrict__ A, const float* __restrict__ B,
              float* __restrict__ C,
              const float* __restrict__ p2)
{
    extern __shared__ float smem[];
    // stage s: A at s*2176 (16x136), B at 8704 + s*4224 (16x264); rsc at 25600
    float* rsc = smem + 4 * (2176 + 4224);

    const int z = blockIdx.z;
    A += (long long)z * NN * NN;
    B += (long long)z * NN * CC;

    const int t    = threadIdx.x;
    const int lane = t & 31;
    const int wid  = t >> 5;        // 0..15
    const int wm   = wid >> 3;      // 0..1
    const int wn   = wid & 7;       // 0..7
    const int grp  = lane >> 2;
    const int qid  = lane & 3;
    const int m0   = blockIdx.y * 128;

    // A staging: thread t covers k-row kk = t>>5 (0..15), cols cq..cq+3
    const int kk = t >> 5, cq = (t & 31) * 4;
    const float* aP = A + (long long)kk * NN + m0 + cq;
    const int aS = kk * 136 + cq;
    // B staging: 2 chunks; chunk ch covers k-row ch>>6, cols (ch&63)*4
    const int bk0 = t >> 6,          bc0 = (t & 63) * 4;
    const int bk1 = (t + 512) >> 6,  bc1 = ((t + 512) & 63) * 4;
    const float* bP0 = B + (long long)bk0 * CC + bc0;
    const float* bP1 = B + (long long)bk1 * CC + bc1;
    const int bS0 = bk0 * 264 + bc0;
    const int bS1 = bk1 * 264 + bc1;

#define ISSUEW(kit)                                                           \
    {                                                                         \
        int s_ = (kit) & 3;                                                   \
        float* As_ = smem + s_ * 2176;                                        \
        float* Bs_ = smem + 8704 + s_ * 4224;                                 \
        long long ko_ = (long long)(kit) * 16;                                \
        cp_async16(smem_u32(As_ + aS),  aP  + ko_ * NN);                      \
        cp_async16(smem_u32(Bs_ + bS0), bP0 + ko_ * CC);                      \
        cp_async16(smem_u32(Bs_ + bS1), bP1 + ko_ * CC);                      \
        asm volatile("cp.async.commit_group;\n");                             \
    }

    float acc[4][4][4];
#pragma unroll
    for (int i = 0; i < 4; i++)
#pragma unroll
        for (int j = 0; j < 4; j++)
#pragma unroll
            for (int e = 0; e < 4; e++) acc[i][j][e] = 0.f;

    float colacc[4] = {0.f, 0.f, 0.f, 0.f};

    const int kIters = NN / 16;   // 128
    ISSUEW(0)
    ISSUEW(1)
    ISSUEW(2)

    for (int kit = 0; kit < kIters; kit++) {
        int rem = kIters - 1 - kit;
        if (rem >= 2)      asm volatile("cp.async.wait_group 2;\n");
        else if (rem == 1) asm volatile("cp.async.wait_group 1;\n");
        else               asm volatile("cp.async.wait_group 0;\n");
        __syncthreads();
        if (kit + 3 < kIters) ISSUEW(kit + 3)

        const float* Ab = smem + (kit & 3) * 2176;
        const float* Bb = smem + 8704 + (kit & 3) * 4224;

        // fused colsum: each attn element staged exactly once per CTA
        {
            float4 ca = *(const float4*)&Ab[aS];
            colacc[0] += ca.x; colacc[1] += ca.y;
            colacc[2] += ca.z; colacc[3] += ca.w;
        }

#pragma unroll
        for (int ks = 0; ks < 16; ks += 8) {
            uint32_t a[4][4], b[4][2];
#pragma unroll
            for (int i = 0; i < 4; i++) {
                int rb = wm * 64 + i * 16 + grp;
                a[i][0] = __float_as_uint(Ab[(ks + qid    ) * 136 + rb]);
                a[i][1] = __float_as_uint(Ab[(ks + qid    ) * 136 + rb + 8]);
                a[i][2] = __float_as_uint(Ab[(ks + qid + 4) * 136 + rb]);
                a[i][3] = __float_as_uint(Ab[(ks + qid + 4) * 136 + rb + 8]);
            }
#pragma unroll
            for (int j = 0; j < 4; j++) {
                int nb = wn * 32 + j * 8 + grp;
                b[j][0] = __float_as_uint(Bb[(ks + qid    ) * 264 + nb]);
                b[j][1] = __float_as_uint(Bb[(ks + qid + 4) * 264 + nb]);
            }
#pragma unroll
            for (int i = 0; i < 4; i++)
#pragma unroll
                for (int j = 0; j < 4; j++) {
                    asm volatile(
                        "mma.sync.aligned.m16n8k8.row.col.f32.tf32.tf32.f32 "
                        "{%0,%1,%2,%3}, {%4,%5,%6,%7}, {%8,%9}, {%0,%1,%2,%3};\n"
                        : "+f"(acc[i][j][0]), "+f"(acc[i][j][1]),
                          "+f"(acc[i][j][2]), "+f"(acc[i][j][3])
                        : "r"(a[i][0]), "r"(a[i][1]), "r"(a[i][2]), "r"(a[i][3]),
                          "r"(b[j][0]), "r"(b[j][1]));
                }
        }
    }
#undef ISSUEW
    __syncthreads();

    // reduce column sums (16 groups x 128 columns) -> rscale
    {
        float* red = smem;
        red[kk * 128 + cq + 0] = colacc[0];
        red[kk * 128 + cq + 1] = colacc[1];
        red[kk * 128 + cq + 2] = colacc[2];
        red[kk * 128 + cq + 3] = colacc[3];
        __syncthreads();
        if (t < 128) {
            float s = 0.f;
#pragma unroll
            for (int gg = 0; gg < 16; gg++) s += red[gg * 128 + t];
            rsc[t] = 1.f / (1e-9f + s);
        }
        __syncthreads();
    }

    float* Cz = C + (long long)z * NN * CC;
    const float* hpz = p2 + (long long)z * NN * CC;
#pragma unroll
    for (int i = 0; i < 4; i++) {
        int r0 = m0 + wm * 64 + i * 16 + grp;
        int r1 = r0 + 8;
        float rsa = rsc[r0 - m0];
        float rsb = rsc[r1 - m0];
#pragma unroll
        for (int j = 0; j < 4; j++) {
            int c = wn * 32 + j * 8 + qid * 2;
            float2 o0, o1;
            o0.x = cvt1(hpz[(long long)r0 * CC + c    ] - acc[i][j][0] * rsa);
            o0.y = cvt1(hpz[(long long)r0 * CC + c + 1] - acc[i][j][1] * rsa);
            o1.x = cvt1(hpz[(long long)r1 * CC + c    ] - acc[i][j][2] * rsb);
            o1.y = cvt1(hpz[(long long)r1 * CC + c + 1] - acc[i][j][3] * rsb);
            *(float2*)&Cz[(long long)r0 * CC + c] = o0;
            *(float2*)&Cz[(long long)r1 * CC + c] = o1;
        }
    }
}

// ---------------- softmax over last dim; writes tf32-rounded probabilities -------
__global__ void softmax_rows(float* __restrict__ attn)
{
    __shared__ float red[256];
    float* p = attn + (long long)blockIdx.x * NN;
    const int t = threadIdx.x;
    float v[8];
    float mx = -1e30f;
#pragma unroll
    for (int i = 0; i < 8; i++) { v[i] = p[t + i*256]; mx = fmaxf(mx, v[i]); }
    red[t] = mx; __syncthreads();
    for (int s = 128; s > 0; s >>= 1) {
        if (t < s) red[t] = fmaxf(red[t], red[t + s]);
        __syncthreads();
    }
    mx = red[0]; __syncthreads();
    float sum = 0.f;
#pragma unroll
    for (int i = 0; i < 8; i++) { v[i] = __expf(v[i] - mx); sum += v[i]; }
    red[t] = sum; __syncthreads();
    for (int s = 128; s > 0; s >>= 1) {
        if (t < s) red[t] += red[t + s];
        __syncthreads();
    }
    float inv = 1.f / red[0];
#pragma unroll
    for (int i = 0; i < 8; i++) p[t + i*256] = cvt1(v[i] * inv);
}

// ==================================================================================
extern "C" void kernel_launch(void* const* d_in, const int* in_sizes, int n_in,
                              void* d_out, int out_size)
{
    const float* x   = (const float*)d_in[0];
    const float* w1  = (const float*)d_in[1];
    const float* w2  = (const float*)d_in[2];
    const float* wqk = (const float*)d_in[3];
    const float* wv  = (const float*)d_in[4];
    const float* bv  = (const float*)d_in[5];
    const float* wt  = (const float*)d_in[6];
    const float* bt  = (const float*)d_in[7];
    const float* bn1g = (const float*)d_in[8],  *bn1b = (const float*)d_in[9];
    const float* bn1m = (const float*)d_in[10], *bn1v = (const float*)d_in[11];
    const float* bn2g = (const float*)d_in[12], *bn2b = (const float*)d_in[13];
    const float* bn2m = (const float*)d_in[14], *bn2v = (const float*)d_in[15];
    const float* bn3g = (const float*)d_in[16], *bn3b = (const float*)d_in[17];
    const float* bn3m = (const float*)d_in[18], *bn3v = (const float*)d_in[19];

    float *h, *q, *v, *u, *attn, *wr, *bns, *bnh;
    cudaGetSymbolAddress((void**)&h, g_h);
    cudaGetSymbolAddress((void**)&q, g_q);
    cudaGetSymbolAddress((void**)&v, g_v);
    cudaGetSymbolAddress((void**)&u, g_u);
    cudaGetSymbolAddress((void**)&attn, g_attn);
    cudaGetSymbolAddress((void**)&wr, g_wr);
    cudaGetSymbolAddress((void**)&bns, g_bnscale);
    cudaGetSymbolAddress((void**)&bnh, g_bnshift);

    float* w2r  = wr;
    float* wqkr = wr + CC*CC;
    float* wvr  = wr + 2*CC*CC;
    float* wtr  = wr + 3*CC*CC;

    cudaFuncSetAttribute(gemm_ca<1>, cudaFuncAttributeMaxDynamicSharedMemorySize, SMEMCA);
    cudaFuncSetAttribute(gemm_ca<2>, cudaFuncAttributeMaxDynamicSharedMemorySize, SMEMCA);
    cudaFuncSetAttribute(gemm_ca<3>, cudaFuncAttributeMaxDynamicSharedMemorySize, SMEMCA);
    cudaFuncSetAttribute(gemm_ca<5>, cudaFuncAttributeMaxDynamicSharedMemorySize, SMEMCA);
    cudaFuncSetAttribute(gemm_ca<6>, cudaFuncAttributeMaxDynamicSharedMemorySize, SMEMCA);
    cudaFuncSetAttribute(gemm_xr2,   cudaFuncAttributeMaxDynamicSharedMemorySize, SMEMXR2);

    bn_prep<<<1, 256>>>(bn1g, bn1b, bn1m, bn1v,
                        bn2g, bn2b, bn2m, bn2v,
                        bn3g, bn3b, bn3m, bn3v, bt);

    // pre-round weights w2,wqk,wv,wt (w1/x rounded inline in gemm_first)
    round_w<<<148, 256>>>(wr, w2, wqk, wv, wt);

    // h1 = cvt(relu(bn1(x @ w1^T)))   (raw x/w1, cvt at STS; into q as temp)
    gemm_first<<<dim3(CC/128, MTOT/128), 256>>>(x, w1, q, bns, bnh);

    // h = cvt(relu(bn2(h1 @ w2^T)))
    gemm_ca<1><<<dim3(CC/128, MTOT/128, 1), 256, SMEMCA>>>(
        q, w2r, h, CC, CC, CC, CC, 0, 0, 0, bns + 256, bnh + 256, nullptr);

    // q = cvt(h @ wqk^T)
    gemm_ca<3><<<dim3(CC/128, MTOT/128, 1), 256, SMEMCA>>>(
        h, wqkr, q, CC, CC, CC, CC, 0, 0, 0, nullptr, nullptr, nullptr);

    // v = cvt(h @ wv^T + bv)
    gemm_ca<2><<<dim3(CC/128, MTOT/128, 1), 256, SMEMCA>>>(
        h, wvr, v, CC, CC, CC, CC, 0, 0, 0, bv, nullptr, nullptr);

    // energy[b,i,j] = q.q  (symmetric, upper-tri pairs, raw store)
    gemm_ca<5><<<dim3(NPAIRS, 1, BB), 256, SMEMCA>>>(
        q, q, attn, CC, CC, CC, NN,
        (long long)NN*CC, (long long)NN*CC, (long long)NN*NN,
        nullptr, nullptr, nullptr);

    // row softmax (writes tf32-rounded probabilities)
    softmax_rows<<<MTOT, 256>>>(attn);

    // u = cvt(h - attn^T @ v * rscale)   *** WIDE BN=256: attn read once ***
    gemm_xr2<<<dim3(1, NN/128, BB), 512, SMEMXR2>>>(attn, v, u, h);

    // out[b,c,i] = h + relu(bn3(u @ wt^T + bt))   (fused, transposed store)
    gemm_ca<6><<<dim3(CC/128, MTOT/128, 1), 256, SMEMCA>>>(
        u, wtr, (float*)d_out, CC, CC, CC, CC, 0, 0, 0, bns + 512, bnh + 512, h);
}

// round 15
// speedup vs baseline: 1.0389x; 1.0389x over previous
#include <cuda_runtime.h>
#include <math.h>
#include <stdint.h>

// Problem constants
#define BB   16
#define NN   2048
#define CIN  64
#define CC   256
#define MTOT (BB*NN)   // 32768
#define NBLK 16        // NN/128
#define NPAIRS 136     // NBLK*(NBLK+1)/2

// cp.async GEMM smem: 4 stages x (2560 A + 2560 B)
#define SMEMCA (8 * 2560 * 4)
// cp.async x_r GEMM smem: 4 stages x (2176 A + 2176 B) + 128 rsc
#define SMEMXR ((8 * 2176 + 128) * 4)

// ---------------- scratch (device globals; no allocation allowed) ----------------
__device__ float g_h[MTOT*CC];
__device__ float g_q[MTOT*CC];
__device__ float g_v[MTOT*CC];
__device__ float g_u[MTOT*CC];
__device__ float g_attn[(size_t)BB*NN*NN];   // 256 MiB
__device__ float g_wr[4*CC*CC];              // rounded w2, wqk, wv, wt (wqk/wv contiguous)
__device__ float g_bnscale[3*CC];
__device__ float g_bnshift[3*CC];

// ---------------- BN precompute ----------------
__global__ void bn_prep(const float* __restrict__ g1, const float* __restrict__ b1,
                        const float* __restrict__ m1, const float* __restrict__ v1,
                        const float* __restrict__ g2, const float* __restrict__ b2,
                        const float* __restrict__ m2, const float* __restrict__ v2,
                        const float* __restrict__ g3, const float* __restrict__ b3,
                        const float* __restrict__ m3, const float* __restrict__ v3,
                        const float* __restrict__ bt)
{
    int c = threadIdx.x;
    float s;
    s = g1[c] * rsqrtf(v1[c] + 1e-5f);
    g_bnscale[c]       = s; g_bnshift[c]       = b1[c] - m1[c]*s;
    s = g2[c] * rsqrtf(v2[c] + 1e-5f);
    g_bnscale[256 + c] = s; g_bnshift[256 + c] = b2[c] - m2[c]*s;
    s = g3[c] * rsqrtf(v3[c] + 1e-5f);
    g_bnscale[512 + c] = s; g_bnshift[512 + c] = (bt[c] - m3[c])*s + b3[c];
}

__device__ __forceinline__ uint32_t cvt_tf32(float x) {
    uint32_t u;
    asm("cvt.rna.tf32.f32 %0, %1;" : "=r"(u) : "f"(x));
    return u;
}
__device__ __forceinline__ float cvt1(float x) { return __uint_as_float(cvt_tf32(x)); }

__device__ __forceinline__ float4 cvt4(float4 v) {
    float4 o;
    o.x = cvt1(v.x); o.y = cvt1(v.y); o.z = cvt1(v.z); o.w = cvt1(v.w);
    return o;
}

__device__ __forceinline__ uint32_t smem_u32(const void* p) {
    return (uint32_t)__cvta_generic_to_shared(p);
}
__device__ __forceinline__ void cp_async16(uint32_t dst, const void* src) {
    asm volatile("cp.async.cg.shared.global [%0], [%1], 16;\n" :: "r"(dst), "l"(src));
}

// ---------------- elementwise tf32 pre-round: 4 weights in one launch -----------
__global__ void round_w(float* __restrict__ dst,
                        const float* __restrict__ s0, const float* __restrict__ s1,
                        const float* __restrict__ s2, const float* __restrict__ s3)
{
    const float* srcs[4] = {s0, s1, s2, s3};
    int tid = blockIdx.x * 256 + threadIdx.x;
    int stride = gridDim.x * 256;
#pragma unroll
    for (int a = 0; a < 4; a++) {
        const float* s = srcs[a];
        float* d = dst + a * CC * CC;
        for (int i = tid * 4; i < CC * CC; i += stride * 4)
            *(float4*)&d[i] = cvt4(*(const float4*)&s[i]);
    }
}

// ====== first GEMM: h1 = cvt(relu(bn1(x @ w1^T))), K=64, raw inputs, cvt@STS =====
__global__ __launch_bounds__(256, 2)
void gemm_first(const float* __restrict__ A, const float* __restrict__ B,
                float* __restrict__ C,
                const float* __restrict__ p0, const float* __restrict__ p1)
{
    __shared__ __align__(16) float As[2][2560];
    __shared__ __align__(16) float Bs[2][2560];

    const int t    = threadIdx.x;
    const int lane = t & 31;
    const int wid  = t >> 5;
    const int wm   = wid >> 2;
    const int wn   = wid & 3;
    const int grp  = lane >> 2;
    const int qid  = lane & 3;
    const int m0   = blockIdx.y * 128;
    const int n0   = blockIdx.x * 128;

    const int idx0 = t, idx1 = t + 256;
    const float* aP0 = A + (long long)(m0 + (idx0 >> 2)) * CIN + (idx0 & 3) * 4;
    const float* aP1 = A + (long long)(m0 + (idx1 >> 2)) * CIN + (idx1 & 3) * 4;
    const float* bP0 = B + (long long)(n0 + (idx0 >> 2)) * CIN + (idx0 & 3) * 4;
    const float* bP1 = B + (long long)(n0 + (idx1 >> 2)) * CIN + (idx1 & 3) * 4;
    const int s0o = (idx0 >> 2) * 20 + (idx0 & 3) * 4;
    const int s1o = (idx1 >> 2) * 20 + (idx1 & 3) * 4;

    float acc[4][4][4];
#pragma unroll
    for (int i = 0; i < 4; i++)
#pragma unroll
        for (int j = 0; j < 4; j++)
#pragma unroll
            for (int e = 0; e < 4; e++) acc[i][j][e] = 0.f;

    float4 stA0, stA1, stB0, stB1;

#define FLDG(kit)                                                        \
    {                                                                    \
        stA0 = *(const float4*)(aP0 + (kit) * 16);                       \
        stA1 = *(const float4*)(aP1 + (kit) * 16);                       \
        stB0 = *(const float4*)(bP0 + (kit) * 16);                       \
        stB1 = *(const float4*)(bP1 + (kit) * 16);                       \
    }
#define FSTS(buf)                                                        \
    {                                                                    \
        *(float4*)&As[buf][s0o] = cvt4(stA0);                            \
        *(float4*)&As[buf][s1o] = cvt4(stA1);                            \
        *(float4*)&Bs[buf][s0o] = cvt4(stB0);                            \
        *(float4*)&Bs[buf][s1o] = cvt4(stB1);                            \
    }

    FLDG(0)
    FSTS(0)
    __syncthreads();

    for (int kit = 0, buf = 0; kit < 4; kit++, buf ^= 1) {
        const bool have_next = (kit + 1) < 4;
        if (have_next) FLDG(kit + 1)

        const float* Ab = As[buf];
        const float* Bb = Bs[buf];
#pragma unroll
        for (int ks = 0; ks < 16; ks += 8) {
            uint32_t a[4][4], b[4][2];
#pragma unroll
            for (int i = 0; i < 4; i++) {
                int rb = wm * 64 + i * 16 + grp;
                a[i][0] = __float_as_uint(Ab[(rb    ) * 20 + ks + qid]);
                a[i][1] = __float_as_uint(Ab[(rb + 8) * 20 + ks + qid]);
                a[i][2] = __float_as_uint(Ab[(rb    ) * 20 + ks + 4 + qid]);
                a[i][3] = __float_as_uint(Ab[(rb + 8) * 20 + ks + 4 + qid]);
            }
#pragma unroll
            for (int j = 0; j < 4; j++) {
                int nb = wn * 32 + j * 8 + grp;
                b[j][0] = __float_as_uint(Bb[nb * 20 + ks + qid]);
                b[j][1] = __float_as_uint(Bb[nb * 20 + ks + 4 + qid]);
            }
#pragma unroll
            for (int i = 0; i < 4; i++)
#pragma unroll
                for (int j = 0; j < 4; j++) {
                    asm volatile(
                        "mma.sync.aligned.m16n8k8.row.col.f32.tf32.tf32.f32 "
                        "{%0,%1,%2,%3}, {%4,%5,%6,%7}, {%8,%9}, {%0,%1,%2,%3};\n"
                        : "+f"(acc[i][j][0]), "+f"(acc[i][j][1]),
                          "+f"(acc[i][j][2]), "+f"(acc[i][j][3])
                        : "r"(a[i][0]), "r"(a[i][1]), "r"(a[i][2]), "r"(a[i][3]),
                          "r"(b[j][0]), "r"(b[j][1]));
                }
        }
        if (have_next) FSTS(buf ^ 1)
        __syncthreads();
    }
#undef FLDG
#undef FSTS

#pragma unroll
    for (int i = 0; i < 4; i++) {
        int r0 = m0 + wm * 64 + i * 16 + grp;
        int r1 = r0 + 8;
#pragma unroll
        for (int j = 0; j < 4; j++) {
            int c = n0 + wn * 32 + j * 8 + qid * 2;
            float s0 = p0[c], s1 = p0[c+1], h0 = p1[c], h1 = p1[c+1];
            float2 o0, o1;
            o0.x = cvt1(fmaxf(acc[i][j][0] * s0 + h0, 0.f));
            o0.y = cvt1(fmaxf(acc[i][j][1] * s1 + h1, 0.f));
            o1.x = cvt1(fmaxf(acc[i][j][2] * s0 + h0, 0.f));
            o1.y = cvt1(fmaxf(acc[i][j][3] * s1 + h1, 0.f));
            *(float2*)&C[(long long)r0 * CC + c] = o0;
            *(float2*)&C[(long long)r1 * CC + c] = o1;
        }
    }
}

// ================= cp.async 4-stage GEMM (operands pre-rounded tf32) =============
// C[m,n] = sum_k A[m*lda+k] * B[n*ldb+k]
// EPI: 1 cvt(relu(acc*p0+p1)); 2 cvt(acc+p0);
//      5 raw symmetric (pair-indexed + mirror);
//      6 fused final: out = p2 + relu(acc*p0+p1), transposed store;
//      7 merged q/v: cols [0,256) -> C = cvt(acc); cols [256,512) -> p2 = cvt(acc+p0[c-256])
template<int EPI>
__global__ __launch_bounds__(256, 2)
void gemm_ca(const float* __restrict__ A, const float* __restrict__ B,
             float* __restrict__ C, int K,
             int lda, int ldb, int ldc,
             long long sA, long long sB, long long sC,
             const float* __restrict__ p0, const float* __restrict__ p1,
             const float* __restrict__ p2)
{
    extern __shared__ float smem[];

    const int z = blockIdx.z;
    A += (long long)z * sA;
    B += (long long)z * sB;

    const int t    = threadIdx.x;
    const int lane = t & 31;
    const int wid  = t >> 5;
    const int wm   = wid >> 2;
    const int wn   = wid & 3;
    const int grp  = lane >> 2;
    const int qid  = lane & 3;

    int m0, n0;
    if (EPI == 5) {
        int rem = blockIdx.x, bi = 0;
        while (rem >= NBLK - bi) { rem -= NBLK - bi; bi++; }
        m0 = bi * 128;
        n0 = (bi + rem) * 128;
    } else {
        m0 = blockIdx.y * 128;
        n0 = blockIdx.x * 128;
    }

    const int row = t >> 2, kq = t & 3;
    const float* aSrc0 = A + (long long)(m0 + row) * lda + kq * 4;
    const float* aSrc1 = aSrc0 + (long long)64 * lda;
    const float* bSrc0 = B + (long long)(n0 + row) * ldb + kq * 4;
    const float* bSrc1 = bSrc0 + (long long)64 * ldb;
    const int off0 = row * 20 + kq * 4;
    const int off1 = off0 + 64 * 20;

#define ISSUE(kit)                                                            \
    {                                                                         \
        int s_ = (kit) & 3;                                                   \
        float* As_ = smem + s_ * 2560;                                        \
        float* Bs_ = smem + 10240 + s_ * 2560;                                \
        long long ko_ = (long long)(kit) * 16;                                \
        cp_async16(smem_u32(As_ + off0), aSrc0 + ko_);                        \
        cp_async16(smem_u32(As_ + off1), aSrc1 + ko_);                        \
        cp_async16(smem_u32(Bs_ + off0), bSrc0 + ko_);                        \
        cp_async16(smem_u32(Bs_ + off1), bSrc1 + ko_);                        \
        asm volatile("cp.async.commit_group;\n");                             \
    }

    float acc[4][4][4];
#pragma unroll
    for (int i = 0; i < 4; i++)
#pragma unroll
        for (int j = 0; j < 4; j++)
#pragma unroll
            for (int e = 0; e < 4; e++) acc[i][j][e] = 0.f;

    const int kIters = K / 16;
    if (0 < kIters) ISSUE(0)
    if (1 < kIters) ISSUE(1)
    if (2 < kIters) ISSUE(2)

    for (int kit = 0; kit < kIters; kit++) {
        int rem = kIters - 1 - kit;
        if (rem >= 2)      asm volatile("cp.async.wait_group 2;\n");
        else if (rem == 1) asm volatile("cp.async.wait_group 1;\n");
        else               asm volatile("cp.async.wait_group 0;\n");
        __syncthreads();
        if (kit + 3 < kIters) ISSUE(kit + 3)

        const float* Ab = smem + (kit & 3) * 2560;
        const float* Bb = smem + 10240 + (kit & 3) * 2560;
#pragma unroll
        for (int ks = 0; ks < 16; ks += 8) {
            uint32_t a[4][4], b[4][2];
#pragma unroll
            for (int i = 0; i < 4; i++) {
                int rb = wm * 64 + i * 16 + grp;
                a[i][0] = __float_as_uint(Ab[(rb    ) * 20 + ks + qid]);
                a[i][1] = __float_as_uint(Ab[(rb + 8) * 20 + ks + qid]);
                a[i][2] = __float_as_uint(Ab[(rb    ) * 20 + ks + 4 + qid]);
                a[i][3] = __float_as_uint(Ab[(rb + 8) * 20 + ks + 4 + qid]);
            }
#pragma unroll
            for (int j = 0; j < 4; j++) {
                int nb = wn * 32 + j * 8 + grp;
                b[j][0] = __float_as_uint(Bb[nb * 20 + ks + qid]);
                b[j][1] = __float_as_uint(Bb[nb * 20 + ks + 4 + qid]);
            }
#pragma unroll
            for (int i = 0; i < 4; i++)
#pragma unroll
                for (int j = 0; j < 4; j++) {
                    asm volatile(
                        "mma.sync.aligned.m16n8k8.row.col.f32.tf32.tf32.f32 "
                        "{%0,%1,%2,%3}, {%4,%5,%6,%7}, {%8,%9}, {%0,%1,%2,%3};\n"
                        : "+f"(acc[i][j][0]), "+f"(acc[i][j][1]),
                          "+f"(acc[i][j][2]), "+f"(acc[i][j][3])
                        : "r"(a[i][0]), "r"(a[i][1]), "r"(a[i][2]), "r"(a[i][3]),
                          "r"(b[j][0]), "r"(b[j][1]));
                }
        }
    }
#undef ISSUE
    __syncthreads();

    float* Cz = C + (long long)z * sC;

    // ---- epilogue: direct store (EPI 1,2,5,7) ----
    if (EPI != 6) {
#pragma unroll
        for (int i = 0; i < 4; i++) {
            int r0 = m0 + wm * 64 + i * 16 + grp;
            int r1 = r0 + 8;
#pragma unroll
            for (int j = 0; j < 4; j++) {
                int c = n0 + wn * 32 + j * 8 + qid * 2;
                float d0 = acc[i][j][0], d1 = acc[i][j][1];
                float d2 = acc[i][j][2], d3 = acc[i][j][3];
                float2 o0, o1;
                if (EPI == 5) {
                    o0 = make_float2(d0, d1);
                    o1 = make_float2(d2, d3);
                    *(float2*)&Cz[(long long)r0 * ldc + c] = o0;
                    *(float2*)&Cz[(long long)r1 * ldc + c] = o1;
                } else if (EPI == 1) {
                    float s0 = p0[c], s1 = p0[c+1], h0 = p1[c], h1 = p1[c+1];
                    o0.x = cvt1(fmaxf(d0 * s0 + h0, 0.f));
                    o0.y = cvt1(fmaxf(d1 * s1 + h1, 0.f));
                    o1.x = cvt1(fmaxf(d2 * s0 + h0, 0.f));
                    o1.y = cvt1(fmaxf(d3 * s1 + h1, 0.f));
                    *(float2*)&Cz[(long long)r0 * ldc + c] = o0;
                    *(float2*)&Cz[(long long)r1 * ldc + c] = o1;
                } else if (EPI == 2) {
                    float h0 = p0[c], h1 = p0[c+1];
                    o0 = make_float2(cvt1(d0 + h0), cvt1(d1 + h1));
                    o1 = make_float2(cvt1(d2 + h0), cvt1(d3 + h1));
                    *(float2*)&Cz[(long long)r0 * ldc + c] = o0;
                    *(float2*)&Cz[(long long)r1 * ldc + c] = o1;
                } else if (EPI == 7) {
                    if (n0 < CC) {
                        // q columns: cvt(acc)
                        o0 = make_float2(cvt1(d0), cvt1(d1));
                        o1 = make_float2(cvt1(d2), cvt1(d3));
                        *(float2*)&Cz[(long long)r0 * ldc + c] = o0;
                        *(float2*)&Cz[(long long)r1 * ldc + c] = o1;
                    } else {
                        // v columns: cvt(acc + bv)
                        int c2 = c - CC;
                        float h0 = p0[c2], h1 = p0[c2+1];
                        o0 = make_float2(cvt1(d0 + h0), cvt1(d1 + h1));
                        o1 = make_float2(cvt1(d2 + h0), cvt1(d3 + h1));
                        float* vz = (float*)p2;
                        *(float2*)&vz[(long long)r0 * ldc + c2] = o0;
                        *(float2*)&vz[(long long)r1 * ldc + c2] = o1;
                    }
                }
            }
        }
    }

    // ---- EPI5 off-diagonal: mirrored (transposed) store via smem staging ----
    if (EPI == 5 && m0 != n0) {
        float* sm_t = smem;
#pragma unroll
        for (int half = 0; half < 2; half++) {
            __syncthreads();
            if (wm == half) {
#pragma unroll
                for (int i = 0; i < 4; i++) {
                    int rl = i * 16 + grp;
#pragma unroll
                    for (int j = 0; j < 4; j++) {
                        int c = wn * 32 + j * 8 + qid * 2;
                        sm_t[rl * 132 + c]           = acc[i][j][0];
                        sm_t[rl * 132 + c + 1]       = acc[i][j][1];
                        sm_t[(rl + 8) * 132 + c]     = acc[i][j][2];
                        sm_t[(rl + 8) * 132 + c + 1] = acc[i][j][3];
                    }
                }
            }
            __syncthreads();
            int c   = t >> 1;
            int seg = (t & 1) * 32;
            float* dst = Cz + (long long)(n0 + c) * ldc + m0 + half * 64 + seg;
#pragma unroll
            for (int s = 0; s < 32; s += 4) {
                float4 o;
                o.x = sm_t[(seg + s + 0) * 132 + c];
                o.y = sm_t[(seg + s + 1) * 132 + c];
                o.z = sm_t[(seg + s + 2) * 132 + c];
                o.w = sm_t[(seg + s + 3) * 132 + c];
                *(float4*)(dst + s) = o;
            }
        }
    }

    // ---- EPI6: out[b,c,i] = p2[r,c] + relu(acc*p0[c]+p1[c]), transposed store ----
    if (EPI == 6) {
#pragma unroll
        for (int i = 0; i < 4; i++) {
            int r0 = m0 + wm * 64 + i * 16 + grp;
            int r1 = r0 + 8;
#pragma unroll
            for (int j = 0; j < 4; j++) {
                int c = n0 + wn * 32 + j * 8 + qid * 2;
                float s0 = p0[c], s1 = p0[c+1], h0 = p1[c], h1 = p1[c+1];
                acc[i][j][0] = p2[(long long)r0 * ldc + c    ] + fmaxf(acc[i][j][0] * s0 + h0, 0.f);
                acc[i][j][1] = p2[(long long)r0 * ldc + c + 1] + fmaxf(acc[i][j][1] * s1 + h1, 0.f);
                acc[i][j][2] = p2[(long long)r1 * ldc + c    ] + fmaxf(acc[i][j][2] * s0 + h0, 0.f);
                acc[i][j][3] = p2[(long long)r1 * ldc + c + 1] + fmaxf(acc[i][j][3] * s1 + h1, 0.f);
            }
        }
        const int zb = m0 >> 11;
        const int ib = m0 & (NN - 1);
        float* outz = C + ((long long)zb * CC + n0) * NN;
        float* sm_t = smem;
#pragma unroll
        for (int half = 0; half < 2; half++) {
            __syncthreads();
            if (wm == half) {
#pragma unroll
                for (int i = 0; i < 4; i++) {
                    int rl = i * 16 + grp;
#pragma unroll
                    for (int j = 0; j < 4; j++) {
                        int c = wn * 32 + j * 8 + qid * 2;
                        sm_t[rl * 132 + c]           = acc[i][j][0];
                        sm_t[rl * 132 + c + 1]       = acc[i][j][1];
                        sm_t[(rl + 8) * 132 + c]     = acc[i][j][2];
                        sm_t[(rl + 8) * 132 + c + 1] = acc[i][j][3];
                    }
                }
            }
            __syncthreads();
            int c   = t >> 1;
            int seg = (t & 1) * 32;
            float* dst = outz + (long long)c * NN + ib + half * 64 + seg;
#pragma unroll
            for (int s = 0; s < 32; s += 4) {
                float4 o;
                o.x = sm_t[(seg + s + 0) * 132 + c];
                o.y = sm_t[(seg + s + 1) * 132 + c];
                o.z = sm_t[(seg + s + 2) * 132 + c];
                o.w = sm_t[(seg + s + 3) * 132 + c];
                *(float4*)(dst + s) = o;
            }
        }
    }
}

// ======= cp.async 4-stage GEMM for x_r: attn^T @ v with fused colsum =============
// (r11-exact: BM=BN=128, 256 threads, colsum from smem readback)
__global__ __launch_bounds__(256, 2)
void gemm_xr(const float* __restrict__ A, const float* __restrict__ B,
             float* __restrict__ C, int K,
             int lda, int ldb, int ldc,
             long long sA, long long sB, long long sC,
             const float* __restrict__ p2)
{
    extern __shared__ float smem[];
    float* rsc = smem + 8 * 2176;

    const int z = blockIdx.z;
    A += (long long)z * sA;
    B += (long long)z * sB;

    const int t    = threadIdx.x;
    const int lane = t & 31;
    const int wid  = t >> 5;
    const int wm   = wid >> 2;
    const int wn   = wid & 3;
    const int grp  = lane >> 2;
    const int qid  = lane & 3;
    const int m0   = blockIdx.y * 128;
    const int n0   = blockIdx.x * 128;

    const int kk = t >> 5, cq = (t & 31) * 4;
    const long long aStep = (long long)lda * 16;
    const long long bStep = (long long)ldb * 16;
    const float* aP0 = A + (long long)kk * lda + m0 + cq;
    const float* aP1 = A + (long long)(kk + 8) * lda + m0 + cq;
    const float* bP0 = B + (long long)kk * ldb + n0 + cq;
    const float* bP1 = B + (long long)(kk + 8) * ldb + n0 + cq;
    const int aS0 = kk * 136 + cq;
    const int aS1 = aS0 + 8 * 136;

#define ISSUEX(kit)                                                           \
    {                                                                         \
        int s_ = (kit) & 3;                                                   \
        float* As_ = smem + s_ * 2176;                                        \
        float* Bs_ = smem + 8704 + s_ * 2176;                                 \
        long long ko_ = (long long)(kit) * aStep;                             \
        long long kb_ = (long long)(kit) * bStep;                             \
        cp_async16(smem_u32(As_ + aS0), aP0 + ko_);                           \
        cp_async16(smem_u32(As_ + aS1), aP1 + ko_);                           \
        cp_async16(smem_u32(Bs_ + aS0), bP0 + kb_);                           \
        cp_async16(smem_u32(Bs_ + aS1), bP1 + kb_);                           \
        asm volatile("cp.async.commit_group;\n");                             \
    }

    float acc[4][4][4];
#pragma unroll
    for (int i = 0; i < 4; i++)
#pragma unroll
        for (int j = 0; j < 4; j++)
#pragma unroll
            for (int e = 0; e < 4; e++) acc[i][j][e] = 0.f;

    float colacc[4] = {0.f, 0.f, 0.f, 0.f};

    const int kIters = K / 16;
    ISSUEX(0)
    ISSUEX(1)
    ISSUEX(2)

    for (int kit = 0; kit < kIters; kit++) {
        int rem = kIters - 1 - kit;
        if (rem >= 2)      asm volatile("cp.async.wait_group 2;\n");
        else if (rem == 1) asm volatile("cp.async.wait_group 1;\n");
        else               asm volatile("cp.async.wait_group 0;\n");
        __syncthreads();
        if (kit + 3 < kIters) ISSUEX(kit + 3)

        const float* Ab = smem + (kit & 3) * 2176;
        const float* Bb = smem + 8704 + (kit & 3) * 2176;

        {
            float4 ca0 = *(const float4*)&Ab[aS0];
            float4 ca1 = *(const float4*)&Ab[aS1];
            colacc[0] += ca0.x + ca1.x;
            colacc[1] += ca0.y + ca1.y;
            colacc[2] += ca0.z + ca1.z;
            colacc[3] += ca0.w + ca1.w;
        }

#pragma unroll
        for (int ks = 0; ks < 16; ks += 8) {
            uint32_t a[4][4], b[4][2];
#pragma unroll
            for (int i = 0; i < 4; i++) {
                int rb = wm * 64 + i * 16 + grp;
                a[i][0] = __float_as_uint(Ab[(ks + qid    ) * 136 + rb]);
                a[i][1] = __float_as_uint(Ab[(ks + qid    ) * 136 + rb + 8]);
                a[i][2] = __float_as_uint(Ab[(ks + qid + 4) * 136 + rb]);
                a[i][3] = __float_as_uint(Ab[(ks + qid + 4) * 136 + rb + 8]);
            }
#pragma unroll
            for (int j = 0; j < 4; j++) {
                int nb = wn * 32 + j * 8 + grp;
                b[j][0] = __float_as_uint(Bb[(ks + qid    ) * 136 + nb]);
                b[j][1] = __float_as_uint(Bb[(ks + qid + 4) * 136 + nb]);
            }
#pragma unroll
            for (int i = 0; i < 4; i++)
#pragma unroll
                for (int j = 0; j < 4; j++) {
                    asm volatile(
                        "mma.sync.aligned.m16n8k8.row.col.f32.tf32.tf32.f32 "
                        "{%0,%1,%2,%3}, {%4,%5,%6,%7}, {%8,%9}, {%0,%1,%2,%3};\n"
                        : "+f"(acc[i][j][0]), "+f"(acc[i][j][1]),
                          "+f"(acc[i][j][2]), "+f"(acc[i][j][3])
                        : "r"(a[i][0]), "r"(a[i][1]), "r"(a[i][2]), "r"(a[i][3]),
                          "r"(b[j][0]), "r"(b[j][1]));
                }
        }
    }
#undef ISSUEX
    __syncthreads();

    {
        float* red = smem;
        red[kk * 128 + cq + 0] = colacc[0];
        red[kk * 128 + cq + 1] = colacc[1];
        red[kk * 128 + cq + 2] = colacc[2];
        red[kk * 128 + cq + 3] = colacc[3];
        __syncthreads();
        if (t < 128) {
            float s = 0.f;
#pragma unroll
            for (int gg = 0; gg < 8; gg++) s += red[gg * 128 + t];
            rsc[t] = 1.f / (1e-9f + s);
        }
        __syncthreads();
    }

    float* Cz = C + (long long)z * sC;
#pragma unroll
    for (int i = 0; i < 4; i++) {
        int r0 = m0 + wm * 64 + i * 16 + grp;
        int r1 = r0 + 8;
        float rsa = rsc[r0 - m0];
        float rsb = rsc[r1 - m0];
#pragma unroll
        for (int j = 0; j < 4; j++) {
            int c = n0 + wn * 32 + j * 8 + qid * 2;
            const float* hpz = p2 + (long long)z * sC;
            float2 o0, o1;
            o0.x = cvt1(hpz[(long long)r0 * ldc + c    ] - acc[i][j][0] * rsa);
            o0.y = cvt1(hpz[(long long)r0 * ldc + c + 1] - acc[i][j][1] * rsa);
            o1.x = cvt1(hpz[(long long)r1 * ldc + c    ] - acc[i][j][2] * rsb);
            o1.y = cvt1(hpz[(long long)r1 * ldc + c + 1] - acc[i][j][3] * rsb);
            *(float2*)&Cz[(long long)r0 * ldc + c] = o0;
            *(float2*)&Cz[(long long)r1 * ldc + c] = o1;
        }
    }
}

// ---------------- softmax over last dim; writes tf32-rounded probabilities -------
__global__ void softmax_rows(float* __restrict__ attn)
{
    __shared__ float red[256];
    float* p = attn + (long long)blockIdx.x * NN;
    const int t = threadIdx.x;
    float v[8];
    float mx = -1e30f;
#pragma unroll
    for (int i = 0; i < 8; i++) { v[i] = p[t + i*256]; mx = fmaxf(mx, v[i]); }
    red[t] = mx; __syncthreads();
    for (int s = 128; s > 0; s >>= 1) {
        if (t < s) red[t] = fmaxf(red[t], red[t + s]);
        __syncthreads();
    }
    mx = red[0]; __syncthreads();
    float sum = 0.f;
#pragma unroll
    for (int i = 0; i < 8; i++) { v[i] = __expf(v[i] - mx); sum += v[i]; }
    red[t] = sum; __syncthreads();
    for (int s = 128; s > 0; s >>= 1) {
        if (t < s) red[t] += red[t + s];
        __syncthreads();
    }
    float inv = 1.f / red[0];
#pragma unroll
    for (int i = 0; i < 8; i++) p[t + i*256] = cvt1(v[i] * inv);
}

// ==================================================================================
extern "C" void kernel_launch(void* const* d_in, const int* in_sizes, int n_in,
                              void* d_out, int out_size)
{
    const float* x   = (const float*)d_in[0];
    const float* w1  = (const float*)d_in[1];
    const float* w2  = (const float*)d_in[2];
    const float* wqk = (const float*)d_in[3];
    const float* wv  = (const float*)d_in[4];
    const float* bv  = (const float*)d_in[5];
    const float* wt  = (const float*)d_in[6];
    const float* bt  = (const float*)d_in[7];
    const float* bn1g = (const float*)d_in[8],  *bn1b = (const float*)d_in[9];
    const float* bn1m = (const float*)d_in[10], *bn1v = (const float*)d_in[11];
    const float* bn2g = (const float*)d_in[12], *bn2b = (const float*)d_in[13];
    const float* bn2m = (const float*)d_in[14], *bn2v = (const float*)d_in[15];
    const float* bn3g = (const float*)d_in[16], *bn3b = (const float*)d_in[17];
    const float* bn3m = (const float*)d_in[18], *bn3v = (const float*)d_in[19];

    float *h, *q, *v, *u, *attn, *wr, *bns, *bnh;
    cudaGetSymbolAddress((void**)&h, g_h);
    cudaGetSymbolAddress((void**)&q, g_q);
    cudaGetSymbolAddress((void**)&v, g_v);
    cudaGetSymbolAddress((void**)&u, g_u);
    cudaGetSymbolAddress((void**)&attn, g_attn);
    cudaGetSymbolAddress((void**)&wr, g_wr);
    cudaGetSymbolAddress((void**)&bns, g_bnscale);
    cudaGetSymbolAddress((void**)&bnh, g_bnshift);

    float* w2r  = wr;
    float* wqkr = wr + CC*CC;     // wqk and wv contiguous for merged qv GEMM
    float* wtr  = wr + 3*CC*CC;

    cudaFuncSetAttribute(gemm_ca<1>, cudaFuncAttributeMaxDynamicSharedMemorySize, SMEMCA);
    cudaFuncSetAttribute(gemm_ca<5>, cudaFuncAttributeMaxDynamicSharedMemorySize, SMEMCA);
    cudaFuncSetAttribute(gemm_ca<6>, cudaFuncAttributeMaxDynamicSharedMemorySize, SMEMCA);
    cudaFuncSetAttribute(gemm_ca<7>, cudaFuncAttributeMaxDynamicSharedMemorySize, SMEMCA);
    cudaFuncSetAttribute(gemm_xr,    cudaFuncAttributeMaxDynamicSharedMemorySize, SMEMXR);

    bn_prep<<<1, 256>>>(bn1g, bn1b, bn1m, bn1v,
                        bn2g, bn2b, bn2m, bn2v,
                        bn3g, bn3b, bn3m, bn3v, bt);

    // pre-round weights w2, wqk, wv, wt (x/w1 rounded inline in gemm_first)
    round_w<<<148, 256>>>(wr, w2, wqk, wv, wt);

    // h1 = cvt(relu(bn1(x @ w1^T)))   (raw x/w1, cvt at STS; into q as temp)
    gemm_first<<<dim3(CC/128, MTOT/128), 256>>>(x, w1, q, bns, bnh);

    // h = cvt(relu(bn2(h1 @ w2^T)))
    gemm_ca<1><<<dim3(CC/128, MTOT/128, 1), 256, SMEMCA>>>(
        q, w2r, h, CC, CC, CC, CC, 0, 0, 0, bns + 256, bnh + 256, nullptr);

    // MERGED: q = cvt(h @ wqk^T), v = cvt(h @ wv^T + bv)   (one launch, shared A)
    gemm_ca<7><<<dim3(2*CC/128, MTOT/128, 1), 256, SMEMCA>>>(
        h, wqkr, q, CC, CC, CC, CC, 0, 0, 0, bv, nullptr, v);

    // energy[b,i,j] = q.q  (symmetric, upper-tri pairs, raw store)
    gemm_ca<5><<<dim3(NPAIRS, 1, BB), 256, SMEMCA>>>(
        q, q, attn, CC, CC, CC, NN,
        (long long)NN*CC, (long long)NN*CC, (long long)NN*NN,
        nullptr, nullptr, nullptr);

    // row softmax (writes tf32-rounded probabilities)
    softmax_rows<<<MTOT, 256>>>(attn);

    // u = cvt(h - attn^T @ v * rscale)   (colsum fused in-CTA; cp.async pipeline)
    gemm_xr<<<dim3(CC/128, NN/128, BB), 256, SMEMXR>>>(
        attn, v, u, NN, NN, CC, CC,
        (long long)NN*NN, (long long)NN*CC, (long long)NN*CC, h);

    // out[b,c,i] = h + relu(bn3(u @ wt^T + bt))   (fused, transposed store)
    gemm_ca<6><<<dim3(CC/128, MTOT/128, 1), 256, SMEMCA>>>(
        u, wtr, (float*)d_out, CC, CC, CC, CC, 0, 0, 0, bns + 512, bnh + 512, h);
}